// round 1
// baseline (speedup 1.0000x reference)
#include <cuda_runtime.h>
#include <math.h>

// Problem constants
#define PB   2
#define PS   2048
#define PE   1024
#define PNH  16
#define PHD  64

// Scratch (device globals -- no cudaMalloc allowed)
__device__ float g_q[PB * PNH * PS * PHD];   // [b,h,s,d]
__device__ float g_k[PB * PNH * PS * PHD];
__device__ float g_v[PB * PNH * PS * PHD];
__device__ float g_cos[PS * 32];             // [s][j], j = pair index 0..31
__device__ float g_sin[PS * 32];

// ---------------------------------------------------------------------------
// Kernel 0: RoPE cos/sin tables
// ---------------------------------------------------------------------------
__global__ void rope_table_kernel() {
    int idx = blockIdx.x * blockDim.x + threadIdx.x;
    if (idx >= PS * 32) return;
    int s = idx >> 5;
    int j = idx & 31;
    float invf = powf(10000.0f, -((float)(2 * j)) / 64.0f);
    float ang = (float)s * invf;
    g_cos[idx] = cosf(ang);
    g_sin[idx] = sinf(ang);
}

// ---------------------------------------------------------------------------
// Kernel 1: QKV GEMM  C[m][n] = sum_k A[m][k] * W[n][k] + bias[n]
// M=4096 (b*2048+s), N=3072 (chunk*1024 + h*64 + d), K=1024
// Fused epilogue: RoPE on q,k chunks; write q/k/v as [b,h,s,d].
// Block tile 64x64, K-tile 32, 256 threads, 4x4 register tiles.
// ---------------------------------------------------------------------------
__global__ __launch_bounds__(256) void qkv_gemm_kernel(
    const float* __restrict__ A,
    const float* __restrict__ Wt,
    const float* __restrict__ bias)
{
    __shared__ __align__(16) float As[32][68];   // [k][m]
    __shared__ __align__(16) float Bs[32][68];   // [k][n]

    int t  = threadIdx.x;
    int tx = t & 15;        // 0..15 -> n sub-tile
    int ty = t >> 4;        // 0..15 -> m sub-tile
    int m0 = blockIdx.y * 64;
    int n0 = blockIdx.x * 64;

    int lr = t >> 3;        // 0..31 (tile row for loads)
    int lk = (t & 7) * 4;   // 0..28 (k offset for float4 load)

    float acc[4][4] = {};

    for (int k0 = 0; k0 < 1024; k0 += 32) {
        __syncthreads();
        #pragma unroll
        for (int pp = 0; pp < 2; pp++) {
            int row = lr + pp * 32;
            float4 av = *(const float4*)&A[(size_t)(m0 + row) * 1024 + k0 + lk];
            As[lk + 0][row] = av.x; As[lk + 1][row] = av.y;
            As[lk + 2][row] = av.z; As[lk + 3][row] = av.w;
            float4 bv = *(const float4*)&Wt[(size_t)(n0 + row) * 1024 + k0 + lk];
            Bs[lk + 0][row] = bv.x; Bs[lk + 1][row] = bv.y;
            Bs[lk + 2][row] = bv.z; Bs[lk + 3][row] = bv.w;
        }
        __syncthreads();
        #pragma unroll
        for (int kk = 0; kk < 32; kk++) {
            float4 a4 = *(const float4*)&As[kk][ty * 4];
            float4 b4 = *(const float4*)&Bs[kk][tx * 4];
            float av[4] = {a4.x, a4.y, a4.z, a4.w};
            float bv[4] = {b4.x, b4.y, b4.z, b4.w};
            #pragma unroll
            for (int i = 0; i < 4; i++)
                #pragma unroll
                for (int j = 0; j < 4; j++)
                    acc[i][j] += av[i] * bv[j];
        }
    }

    // Epilogue: bias + RoPE + scatter to head-major layout
    int chunk = n0 >> 10;            // 0=q 1=k 2=v (constant per block)
    int h     = (n0 & 1023) >> 6;    // head (constant per block)
    int dbase = tx * 4;              // d offset in 0..60 (n0 % 64 == 0)

    float bj[4];
    #pragma unroll
    for (int j = 0; j < 4; j++) bj[j] = bias[n0 + tx * 4 + j];

    float* dst = (chunk == 0) ? g_q : (chunk == 1) ? g_k : g_v;

    #pragma unroll
    for (int i = 0; i < 4; i++) {
        int m = m0 + ty * 4 + i;
        int b = m >> 11;
        int s = m & 2047;
        float r0 = acc[i][0] + bj[0];
        float r1 = acc[i][1] + bj[1];
        float r2 = acc[i][2] + bj[2];
        float r3 = acc[i][3] + bj[3];
        float4 wv;
        if (chunk < 2) {
            int jp = tx * 2;  // pair index = d/2
            float c0 = g_cos[s * 32 + jp],     s0 = g_sin[s * 32 + jp];
            float c1 = g_cos[s * 32 + jp + 1], s1 = g_sin[s * 32 + jp + 1];
            wv.x = r0 * c0 - r1 * s0;
            wv.y = r0 * s0 + r1 * c0;
            wv.z = r2 * c1 - r3 * s1;
            wv.w = r2 * s1 + r3 * c1;
        } else {
            wv = make_float4(r0, r1, r2, r3);
        }
        *(float4*)&dst[(((size_t)(b * PNH + h)) * PS + s) * PHD + dbase] = wv;
    }
}

// ---------------------------------------------------------------------------
// Kernel 2: flash-attention (non-causal full softmax)
// Grid: (32 q-tiles, 32 bh). 128 threads/CTA.
// Q tile 64x64 resident; stream 32-key K/V tiles with online softmax.
// ---------------------------------------------------------------------------
__global__ __launch_bounds__(128) void attention_kernel(float* __restrict__ out) {
    __shared__ __align__(16) float Qs[64][68];   // [d][r] transposed
    __shared__ __align__(16) float Ks[64][36];   // [d][c] transposed
    __shared__ __align__(16) float Vs[32][64];   // [j][d] natural
    __shared__ float Sst[64][33];                // scores / probabilities
    __shared__ float m_s[64], l_s[64], rscale[64];

    int t  = threadIdx.x;
    int tx = t & 7;    // 0..7
    int ty = t >> 3;   // 0..15
    int bh = blockIdx.y;
    int q0 = blockIdx.x * 64;

    const float* Qg = g_q + (size_t)bh * PS * PHD;
    const float* Kg = g_k + (size_t)bh * PS * PHD;
    const float* Vg = g_v + (size_t)bh * PS * PHD;

    // Load Q tile transposed: Qs[d][r]
    #pragma unroll
    for (int p = 0; p < 8; p++) {
        int idx = p * 128 + t;
        int r  = idx >> 4;          // 0..63
        int d4 = (idx & 15) * 4;    // 0..60
        float4 v = *(const float4*)&Qg[(size_t)(q0 + r) * 64 + d4];
        Qs[d4 + 0][r] = v.x; Qs[d4 + 1][r] = v.y;
        Qs[d4 + 2][r] = v.z; Qs[d4 + 3][r] = v.w;
    }
    if (t < 64) { m_s[t] = -1e30f; l_s[t] = 0.0f; }

    float o[4][8] = {};

    for (int kt = 0; kt < PS; kt += 32) {
        __syncthreads();  // previous iteration fully consumed Vs/Sst

        // Load K tile transposed: Ks[d][c]
        #pragma unroll
        for (int p = 0; p < 4; p++) {
            int idx = p * 128 + t;
            int c  = idx >> 4;          // 0..31
            int d4 = (idx & 15) * 4;
            float4 v = *(const float4*)&Kg[(size_t)(kt + c) * 64 + d4];
            Ks[d4 + 0][c] = v.x; Ks[d4 + 1][c] = v.y;
            Ks[d4 + 2][c] = v.z; Ks[d4 + 3][c] = v.w;
        }
        // Load V tile natural: Vs[j][d]
        #pragma unroll
        for (int p = 0; p < 4; p++) {
            int idx = p * 128 + t;
            int j  = idx >> 4;
            int d4 = (idx & 15) * 4;
            *(float4*)&Vs[j][d4] = *(const float4*)&Vg[(size_t)(kt + j) * 64 + d4];
        }
        __syncthreads();

        // S = Q K^T * scale  (64 rows x 32 cols), 4x4 register tiles
        {
            float sacc[4][4] = {};
            #pragma unroll
            for (int d = 0; d < 64; d++) {
                float4 a4 = *(const float4*)&Qs[d][ty * 4];
                float4 b4 = *(const float4*)&Ks[d][tx * 4];
                float av[4] = {a4.x, a4.y, a4.z, a4.w};
                float bv[4] = {b4.x, b4.y, b4.z, b4.w};
                #pragma unroll
                for (int i = 0; i < 4; i++)
                    #pragma unroll
                    for (int j = 0; j < 4; j++)
                        sacc[i][j] += av[i] * bv[j];
            }
            #pragma unroll
            for (int i = 0; i < 4; i++)
                #pragma unroll
                for (int j = 0; j < 4; j++)
                    Sst[ty * 4 + i][tx * 4 + j] = sacc[i][j] * 0.125f;
        }
        __syncthreads();

        // Online softmax: 2 threads per row, 16 cols each
        {
            int r = t >> 1, half = t & 1;
            float vals[16];
            float mloc = -1e30f;
            #pragma unroll
            for (int j = 0; j < 16; j++) {
                vals[j] = Sst[r][half * 16 + j];
                mloc = fmaxf(mloc, vals[j]);
            }
            mloc = fmaxf(mloc, __shfl_xor_sync(0xffffffffu, mloc, 1));
            float mold = m_s[r];
            float mnew = fmaxf(mold, mloc);
            float f = __expf(mold - mnew);
            float sum = 0.0f;
            #pragma unroll
            for (int j = 0; j < 16; j++) {
                float p_ = __expf(vals[j] - mnew);
                Sst[r][half * 16 + j] = p_;
                sum += p_;
            }
            sum += __shfl_xor_sync(0xffffffffu, sum, 1);
            if (half == 0) {
                m_s[r] = mnew;
                l_s[r] = l_s[r] * f + sum;
                rscale[r] = f;
            }
        }
        __syncthreads();

        // O = O*f + P @ V  (64x64, thread tile 4 rows x 8 cols)
        #pragma unroll
        for (int i = 0; i < 4; i++) {
            float f = rscale[ty * 4 + i];
            #pragma unroll
            for (int jj = 0; jj < 8; jj++) o[i][jj] *= f;
        }
        #pragma unroll 4
        for (int j = 0; j < 32; j++) {
            float pr[4];
            #pragma unroll
            for (int i = 0; i < 4; i++) pr[i] = Sst[ty * 4 + i][j];
            float4 v0 = *(const float4*)&Vs[j][tx * 8];
            float4 v1 = *(const float4*)&Vs[j][tx * 8 + 4];
            float vv[8] = {v0.x, v0.y, v0.z, v0.w, v1.x, v1.y, v1.z, v1.w};
            #pragma unroll
            for (int i = 0; i < 4; i++)
                #pragma unroll
                for (int jj = 0; jj < 8; jj++)
                    o[i][jj] += pr[i] * vv[jj];
        }
    }
    __syncthreads();

    // Epilogue: divide by l, write out [b, s, h*64+d]
    int b = bh >> 4, h = bh & 15;
    #pragma unroll
    for (int i = 0; i < 4; i++) {
        float inv = 1.0f / l_s[ty * 4 + i];
        int srow = q0 + ty * 4 + i;
        size_t base = ((size_t)(b * PS + srow)) * PE + h * 64 + tx * 8;
        float4 w0, w1;
        w0.x = o[i][0] * inv; w0.y = o[i][1] * inv;
        w0.z = o[i][2] * inv; w0.w = o[i][3] * inv;
        w1.x = o[i][4] * inv; w1.y = o[i][5] * inv;
        w1.z = o[i][6] * inv; w1.w = o[i][7] * inv;
        *(float4*)&out[base] = w0;
        *(float4*)&out[base + 4] = w1;
    }
}

// ---------------------------------------------------------------------------
extern "C" void kernel_launch(void* const* d_in, const int* in_sizes, int n_in,
                              void* d_out, int out_size) {
    const float* hs   = (const float*)d_in[0];  // [2,2048,1024]
    const float* w    = (const float*)d_in[1];  // [3072,1024]
    const float* bias = (const float*)d_in[2];  // [3072]
    float* out = (float*)d_out;                 // [2,2048,1024]

    rope_table_kernel<<<256, 256>>>();
    qkv_gemm_kernel<<<dim3(48, 64), 256>>>(hs, w, bias);
    attention_kernel<<<dim3(32, 32), 128>>>(out);
}

// round 2
// speedup vs baseline: 2.7928x; 2.7928x over previous
#include <cuda_runtime.h>
#include <math.h>
#include <stdint.h>

#define PB   2
#define PS   2048
#define PE   1024
#define PNH  16
#define PHD  64

__device__ float g_q[PB * PNH * PS * PHD];   // [b,h,s,d]
__device__ float g_k[PB * PNH * PS * PHD];
__device__ float g_v[PB * PNH * PS * PHD];
__device__ float g_cos[PS * 32];
__device__ float g_sin[PS * 32];

// ---------------------------------------------------------------------------
__device__ __forceinline__ uint32_t f2tf(float f) {
    uint32_t u;
    asm("cvt.rna.tf32.f32 %0, %1;" : "=r"(u) : "f"(f));
    return u;
}

__device__ __forceinline__ void mma8(float* c,
                                     uint32_t a0, uint32_t a1, uint32_t a2, uint32_t a3,
                                     uint32_t b0, uint32_t b1) {
    asm volatile(
        "mma.sync.aligned.m16n8k8.row.col.f32.tf32.tf32.f32 "
        "{%0,%1,%2,%3}, {%4,%5,%6,%7}, {%8,%9}, {%0,%1,%2,%3};"
        : "+f"(c[0]), "+f"(c[1]), "+f"(c[2]), "+f"(c[3])
        : "r"(a0), "r"(a1), "r"(a2), "r"(a3), "r"(b0), "r"(b1));
}

// ---------------------------------------------------------------------------
// Kernel 0: RoPE cos/sin tables
// ---------------------------------------------------------------------------
__global__ void rope_table_kernel() {
    int idx = blockIdx.x * blockDim.x + threadIdx.x;
    if (idx >= PS * 32) return;
    int s = idx >> 5;
    int j = idx & 31;
    float invf = powf(10000.0f, -((float)(2 * j)) / 64.0f);
    float ang = (float)s * invf;
    g_cos[idx] = cosf(ang);
    g_sin[idx] = sinf(ang);
}

// ---------------------------------------------------------------------------
// Kernel 1: QKV GEMM, TF32 tensor cores.
// C[m][n] = sum_k A[m][k]*W[n][k] + bias[n];  M=4096 N=3072 K=1024
// Block 128x128, K-tile 16, 256 thr = 8 warps (2m x 4n), warp tile 64x32.
// Epilogue: RoPE on q/k, scatter to [b,h,s,d].
// ---------------------------------------------------------------------------
__global__ __launch_bounds__(256) void qkv_gemm_kernel(
    const float* __restrict__ A,
    const float* __restrict__ W,
    const float* __restrict__ bias)
{
    __shared__ uint32_t As[2][128][20];   // [m][k], stride 20 (== 4 mod 32)
    __shared__ uint32_t Bs[2][128][20];   // [n][k]

    int t = threadIdx.x;
    int lane = t & 31, w = t >> 5;
    int g = lane >> 2, q = lane & 3;
    int wm = w >> 2, wn = w & 3;
    int m0 = blockIdx.y * 128, n0 = blockIdx.x * 128;

    float c[4][4][4] = {};

    float4 pa[2], pb[2];
    #pragma unroll
    for (int p = 0; p < 2; p++) {
        int idx = p * 256 + t, row = idx >> 2, kq = (idx & 3) * 4;
        pa[p] = *(const float4*)&A[(size_t)(m0 + row) * 1024 + kq];
        pb[p] = *(const float4*)&W[(size_t)(n0 + row) * 1024 + kq];
    }
    #pragma unroll
    for (int p = 0; p < 2; p++) {
        int idx = p * 256 + t, row = idx >> 2, kq = (idx & 3) * 4;
        *(uint4*)&As[0][row][kq] = make_uint4(f2tf(pa[p].x), f2tf(pa[p].y), f2tf(pa[p].z), f2tf(pa[p].w));
        *(uint4*)&Bs[0][row][kq] = make_uint4(f2tf(pb[p].x), f2tf(pb[p].y), f2tf(pb[p].z), f2tf(pb[p].w));
    }
    __syncthreads();

    for (int kt = 0; kt < 64; kt++) {
        int buf = kt & 1;
        if (kt < 63) {
            int k0 = (kt + 1) * 16;
            #pragma unroll
            for (int p = 0; p < 2; p++) {
                int idx = p * 256 + t, row = idx >> 2, kq = (idx & 3) * 4;
                pa[p] = *(const float4*)&A[(size_t)(m0 + row) * 1024 + k0 + kq];
                pb[p] = *(const float4*)&W[(size_t)(n0 + row) * 1024 + k0 + kq];
            }
        }
        #pragma unroll
        for (int kf = 0; kf < 2; kf++) {
            uint32_t a[4][4];
            #pragma unroll
            for (int mi = 0; mi < 4; mi++) {
                int r = wm * 64 + mi * 16 + g;
                a[mi][0] = As[buf][r][kf * 8 + q];
                a[mi][1] = As[buf][r + 8][kf * 8 + q];
                a[mi][2] = As[buf][r][kf * 8 + q + 4];
                a[mi][3] = As[buf][r + 8][kf * 8 + q + 4];
            }
            #pragma unroll
            for (int ni = 0; ni < 4; ni++) {
                int rn = wn * 32 + ni * 8 + g;
                uint32_t b0 = Bs[buf][rn][kf * 8 + q];
                uint32_t b1 = Bs[buf][rn][kf * 8 + q + 4];
                #pragma unroll
                for (int mi = 0; mi < 4; mi++)
                    mma8(c[mi][ni], a[mi][0], a[mi][1], a[mi][2], a[mi][3], b0, b1);
            }
        }
        if (kt < 63) {
            #pragma unroll
            for (int p = 0; p < 2; p++) {
                int idx = p * 256 + t, row = idx >> 2, kq = (idx & 3) * 4;
                *(uint4*)&As[buf ^ 1][row][kq] = make_uint4(f2tf(pa[p].x), f2tf(pa[p].y), f2tf(pa[p].z), f2tf(pa[p].w));
                *(uint4*)&Bs[buf ^ 1][row][kq] = make_uint4(f2tf(pb[p].x), f2tf(pb[p].y), f2tf(pb[p].z), f2tf(pb[p].w));
            }
            __syncthreads();
        }
    }

    // Epilogue: bias + RoPE + scatter
    int chunk = n0 >> 10;   // constant per block (128 | 1024)
    float* dst = (chunk == 0) ? g_q : (chunk == 1) ? g_k : g_v;

    #pragma unroll
    for (int mi = 0; mi < 4; mi++) {
        #pragma unroll
        for (int ni = 0; ni < 4; ni++) {
            int nn = n0 + wn * 32 + ni * 8 + 2 * q;   // even col
            int h  = (nn & 1023) >> 6;
            int d  = nn & 63;
            float b0v = bias[nn], b1v = bias[nn + 1];
            #pragma unroll
            for (int half = 0; half < 2; half++) {
                int m = m0 + wm * 64 + mi * 16 + g + half * 8;
                int b = m >> 11, s = m & 2047;
                float x = c[mi][ni][half * 2 + 0] + b0v;
                float y = c[mi][ni][half * 2 + 1] + b1v;
                float2 wv;
                if (chunk < 2) {
                    int jp = d >> 1;
                    float cc = g_cos[s * 32 + jp], ss = g_sin[s * 32 + jp];
                    wv.x = x * cc - y * ss;
                    wv.y = x * ss + y * cc;
                } else {
                    wv.x = x; wv.y = y;
                }
                *(float2*)&dst[(((size_t)(b * PNH + h)) * PS + s) * PHD + d] = wv;
            }
        }
    }
}

// ---------------------------------------------------------------------------
// Kernel 2: flash attention, TF32 tensor cores.
// Grid (32 q-tiles, 32 bh), 128 thr = 4 warps. Q tile 64x64 resident,
// stream 32-key K/V tiles. Warp w owns rows 16w..16w+15 (full softmax rows).
// ---------------------------------------------------------------------------
__global__ __launch_bounds__(128) void attention_kernel(float* __restrict__ out) {
    __shared__ uint32_t Qs[64][68];   // [q][d]
    __shared__ uint32_t Ks[32][68];   // [key][d]
    __shared__ uint32_t Vs[64][36];   // [d][key] transposed
    __shared__ uint32_t Ps[64][36];   // [q][key]

    int t = threadIdx.x, lane = t & 31, w = t >> 5;
    int g = lane >> 2, q = lane & 3;
    int bh = blockIdx.y, q0 = blockIdx.x * 64;

    const float* Qg = g_q + (size_t)bh * PS * PHD;
    const float* Kg = g_k + (size_t)bh * PS * PHD;
    const float* Vg = g_v + (size_t)bh * PS * PHD;

    #pragma unroll
    for (int p = 0; p < 8; p++) {
        int idx = p * 128 + t, row = idx >> 4, dq = (idx & 15) * 4;
        float4 v = *(const float4*)&Qg[(size_t)(q0 + row) * 64 + dq];
        *(uint4*)&Qs[row][dq] = make_uint4(f2tf(v.x), f2tf(v.y), f2tf(v.z), f2tf(v.w));
    }

    float O[8][4] = {};
    float m0v = -1e30f, m1v = -1e30f;
    float l0v = 0.0f, l1v = 0.0f;

    for (int kt = 0; kt < PS; kt += 32) {
        __syncthreads();   // prev iter fully consumed Ks/Vs (also covers Q load)

        #pragma unroll
        for (int p = 0; p < 4; p++) {
            int idx = p * 128 + t, row = idx >> 4, dq = (idx & 15) * 4;
            float4 v = *(const float4*)&Kg[(size_t)(kt + row) * 64 + dq];
            *(uint4*)&Ks[row][dq] = make_uint4(f2tf(v.x), f2tf(v.y), f2tf(v.z), f2tf(v.w));
        }
        #pragma unroll
        for (int p = 0; p < 4; p++) {
            int idx = p * 128 + t, row = idx >> 4, dq = (idx & 15) * 4;
            float4 v = *(const float4*)&Vg[(size_t)(kt + row) * 64 + dq];
            Vs[dq + 0][row] = f2tf(v.x);
            Vs[dq + 1][row] = f2tf(v.y);
            Vs[dq + 2][row] = f2tf(v.z);
            Vs[dq + 3][row] = f2tf(v.w);
        }
        __syncthreads();

        // S = Q K^T (warp tile 16 x 32)
        float s[4][4] = {};
        #pragma unroll
        for (int kf = 0; kf < 8; kf++) {
            uint32_t a0 = Qs[16 * w + g][kf * 8 + q];
            uint32_t a1 = Qs[16 * w + g + 8][kf * 8 + q];
            uint32_t a2 = Qs[16 * w + g][kf * 8 + q + 4];
            uint32_t a3 = Qs[16 * w + g + 8][kf * 8 + q + 4];
            #pragma unroll
            for (int ni = 0; ni < 4; ni++) {
                uint32_t b0 = Ks[ni * 8 + g][kf * 8 + q];
                uint32_t b1 = Ks[ni * 8 + g][kf * 8 + q + 4];
                mma8(s[ni], a0, a1, a2, a3, b0, b1);
            }
        }

        // Online softmax over this warp's 2 rows per thread
        float ml0 = -1e30f, ml1 = -1e30f;
        #pragma unroll
        for (int ni = 0; ni < 4; ni++) {
            #pragma unroll
            for (int j = 0; j < 4; j++) s[ni][j] *= 0.125f;
            ml0 = fmaxf(ml0, fmaxf(s[ni][0], s[ni][1]));
            ml1 = fmaxf(ml1, fmaxf(s[ni][2], s[ni][3]));
        }
        ml0 = fmaxf(ml0, __shfl_xor_sync(0xffffffffu, ml0, 1));
        ml0 = fmaxf(ml0, __shfl_xor_sync(0xffffffffu, ml0, 2));
        ml1 = fmaxf(ml1, __shfl_xor_sync(0xffffffffu, ml1, 1));
        ml1 = fmaxf(ml1, __shfl_xor_sync(0xffffffffu, ml1, 2));

        float mn0 = fmaxf(m0v, ml0), mn1 = fmaxf(m1v, ml1);
        float f0 = __expf(m0v - mn0), f1 = __expf(m1v - mn1);
        m0v = mn0; m1v = mn1;

        float sum0 = 0.0f, sum1 = 0.0f;
        #pragma unroll
        for (int ni = 0; ni < 4; ni++) {
            float p0 = __expf(s[ni][0] - mn0);
            float p1 = __expf(s[ni][1] - mn0);
            float p2 = __expf(s[ni][2] - mn1);
            float p3 = __expf(s[ni][3] - mn1);
            sum0 += p0 + p1;
            sum1 += p2 + p3;
            *(uint2*)&Ps[16 * w + g][ni * 8 + 2 * q]     = make_uint2(f2tf(p0), f2tf(p1));
            *(uint2*)&Ps[16 * w + g + 8][ni * 8 + 2 * q] = make_uint2(f2tf(p2), f2tf(p3));
        }
        sum0 += __shfl_xor_sync(0xffffffffu, sum0, 1);
        sum0 += __shfl_xor_sync(0xffffffffu, sum0, 2);
        sum1 += __shfl_xor_sync(0xffffffffu, sum1, 1);
        sum1 += __shfl_xor_sync(0xffffffffu, sum1, 2);
        l0v = l0v * f0 + sum0;
        l1v = l1v * f1 + sum1;

        #pragma unroll
        for (int nf = 0; nf < 8; nf++) {
            O[nf][0] *= f0; O[nf][1] *= f0;
            O[nf][2] *= f1; O[nf][3] *= f1;
        }
        __syncwarp();

        // O += P V  (warp reads only its own 16 Ps rows)
        #pragma unroll
        for (int kf = 0; kf < 4; kf++) {
            uint32_t a0 = Ps[16 * w + g][kf * 8 + q];
            uint32_t a1 = Ps[16 * w + g + 8][kf * 8 + q];
            uint32_t a2 = Ps[16 * w + g][kf * 8 + q + 4];
            uint32_t a3 = Ps[16 * w + g + 8][kf * 8 + q + 4];
            #pragma unroll
            for (int nf = 0; nf < 8; nf++) {
                uint32_t b0 = Vs[nf * 8 + g][kf * 8 + q];
                uint32_t b1 = Vs[nf * 8 + g][kf * 8 + q + 4];
                mma8(O[nf], a0, a1, a2, a3, b0, b1);
            }
        }
    }

    // Epilogue
    int b = bh >> 4, h = bh & 15;
    float inv0 = 1.0f / l0v, inv1 = 1.0f / l1v;
    int s0r = q0 + 16 * w + g, s1r = s0r + 8;
    #pragma unroll
    for (int nf = 0; nf < 8; nf++) {
        int d = nf * 8 + 2 * q;
        float2 w0 = make_float2(O[nf][0] * inv0, O[nf][1] * inv0);
        float2 w1 = make_float2(O[nf][2] * inv1, O[nf][3] * inv1);
        *(float2*)&out[((size_t)(b * PS + s0r)) * PE + h * 64 + d] = w0;
        *(float2*)&out[((size_t)(b * PS + s1r)) * PE + h * 64 + d] = w1;
    }
}

// ---------------------------------------------------------------------------
extern "C" void kernel_launch(void* const* d_in, const int* in_sizes, int n_in,
                              void* d_out, int out_size) {
    const float* hs   = (const float*)d_in[0];  // [2,2048,1024]
    const float* w    = (const float*)d_in[1];  // [3072,1024]
    const float* bias = (const float*)d_in[2];  // [3072]
    float* out = (float*)d_out;                 // [2,2048,1024]

    rope_table_kernel<<<256, 256>>>();
    qkv_gemm_kernel<<<dim3(24, 32), 256>>>(hs, w, bias);
    attention_kernel<<<dim3(32, 32), 128>>>(out);
}

// round 3
// speedup vs baseline: 3.6960x; 1.3234x over previous
#include <cuda_runtime.h>
#include <math.h>
#include <stdint.h>

#define PB   2
#define PS   2048
#define PE   1024
#define PNH  16
#define PHD  64

__device__ float g_q[PB * PNH * PS * PHD];   // [b,h,s,d]
__device__ float g_k[PB * PNH * PS * PHD];
__device__ float g_v[PB * PNH * PS * PHD];
__device__ float g_cos[PS * 32];
__device__ float g_sin[PS * 32];

// ---------------------------------------------------------------------------
__device__ __forceinline__ uint32_t f2tf(float f) {
    uint32_t u;
    asm("cvt.rna.tf32.f32 %0, %1;" : "=r"(u) : "f"(f));
    return u;
}

__device__ __forceinline__ void mma8(float* c,
                                     uint32_t a0, uint32_t a1, uint32_t a2, uint32_t a3,
                                     uint32_t b0, uint32_t b1) {
    asm volatile(
        "mma.sync.aligned.m16n8k8.row.col.f32.tf32.tf32.f32 "
        "{%0,%1,%2,%3}, {%4,%5,%6,%7}, {%8,%9}, {%0,%1,%2,%3};"
        : "+f"(c[0]), "+f"(c[1]), "+f"(c[2]), "+f"(c[3])
        : "r"(a0), "r"(a1), "r"(a2), "r"(a3), "r"(b0), "r"(b1));
}

// ---------------------------------------------------------------------------
// Kernel 0: RoPE cos/sin tables
// ---------------------------------------------------------------------------
__global__ void rope_table_kernel() {
    int idx = blockIdx.x * blockDim.x + threadIdx.x;
    if (idx >= PS * 32) return;
    int s = idx >> 5;
    int j = idx & 31;
    float invf = powf(10000.0f, -((float)(2 * j)) / 64.0f);
    float ang = (float)s * invf;
    g_cos[idx] = cosf(ang);
    g_sin[idx] = sinf(ang);
}

// ---------------------------------------------------------------------------
// Kernel 1: QKV GEMM, TF32 tensor cores (unchanged from round 2).
// ---------------------------------------------------------------------------
__global__ __launch_bounds__(256) void qkv_gemm_kernel(
    const float* __restrict__ A,
    const float* __restrict__ W,
    const float* __restrict__ bias)
{
    __shared__ uint32_t As[2][128][20];
    __shared__ uint32_t Bs[2][128][20];

    int t = threadIdx.x;
    int lane = t & 31, w = t >> 5;
    int g = lane >> 2, q = lane & 3;
    int wm = w >> 2, wn = w & 3;
    int m0 = blockIdx.y * 128, n0 = blockIdx.x * 128;

    float c[4][4][4] = {};

    float4 pa[2], pb[2];
    #pragma unroll
    for (int p = 0; p < 2; p++) {
        int idx = p * 256 + t, row = idx >> 2, kq = (idx & 3) * 4;
        pa[p] = *(const float4*)&A[(size_t)(m0 + row) * 1024 + kq];
        pb[p] = *(const float4*)&W[(size_t)(n0 + row) * 1024 + kq];
    }
    #pragma unroll
    for (int p = 0; p < 2; p++) {
        int idx = p * 256 + t, row = idx >> 2, kq = (idx & 3) * 4;
        *(uint4*)&As[0][row][kq] = make_uint4(f2tf(pa[p].x), f2tf(pa[p].y), f2tf(pa[p].z), f2tf(pa[p].w));
        *(uint4*)&Bs[0][row][kq] = make_uint4(f2tf(pb[p].x), f2tf(pb[p].y), f2tf(pb[p].z), f2tf(pb[p].w));
    }
    __syncthreads();

    for (int kt = 0; kt < 64; kt++) {
        int buf = kt & 1;
        if (kt < 63) {
            int k0 = (kt + 1) * 16;
            #pragma unroll
            for (int p = 0; p < 2; p++) {
                int idx = p * 256 + t, row = idx >> 2, kq = (idx & 3) * 4;
                pa[p] = *(const float4*)&A[(size_t)(m0 + row) * 1024 + k0 + kq];
                pb[p] = *(const float4*)&W[(size_t)(n0 + row) * 1024 + k0 + kq];
            }
        }
        #pragma unroll
        for (int kf = 0; kf < 2; kf++) {
            uint32_t a[4][4];
            #pragma unroll
            for (int mi = 0; mi < 4; mi++) {
                int r = wm * 64 + mi * 16 + g;
                a[mi][0] = As[buf][r][kf * 8 + q];
                a[mi][1] = As[buf][r + 8][kf * 8 + q];
                a[mi][2] = As[buf][r][kf * 8 + q + 4];
                a[mi][3] = As[buf][r + 8][kf * 8 + q + 4];
            }
            #pragma unroll
            for (int ni = 0; ni < 4; ni++) {
                int rn = wn * 32 + ni * 8 + g;
                uint32_t b0 = Bs[buf][rn][kf * 8 + q];
                uint32_t b1 = Bs[buf][rn][kf * 8 + q + 4];
                #pragma unroll
                for (int mi = 0; mi < 4; mi++)
                    mma8(c[mi][ni], a[mi][0], a[mi][1], a[mi][2], a[mi][3], b0, b1);
            }
        }
        if (kt < 63) {
            #pragma unroll
            for (int p = 0; p < 2; p++) {
                int idx = p * 256 + t, row = idx >> 2, kq = (idx & 3) * 4;
                *(uint4*)&As[buf ^ 1][row][kq] = make_uint4(f2tf(pa[p].x), f2tf(pa[p].y), f2tf(pa[p].z), f2tf(pa[p].w));
                *(uint4*)&Bs[buf ^ 1][row][kq] = make_uint4(f2tf(pb[p].x), f2tf(pb[p].y), f2tf(pb[p].z), f2tf(pb[p].w));
            }
            __syncthreads();
        }
    }

    int chunk = n0 >> 10;
    float* dst = (chunk == 0) ? g_q : (chunk == 1) ? g_k : g_v;

    #pragma unroll
    for (int mi = 0; mi < 4; mi++) {
        #pragma unroll
        for (int ni = 0; ni < 4; ni++) {
            int nn = n0 + wn * 32 + ni * 8 + 2 * q;
            int h  = (nn & 1023) >> 6;
            int d  = nn & 63;
            float b0v = bias[nn], b1v = bias[nn + 1];
            #pragma unroll
            for (int half = 0; half < 2; half++) {
                int m = m0 + wm * 64 + mi * 16 + g + half * 8;
                int b = m >> 11, s = m & 2047;
                float x = c[mi][ni][half * 2 + 0] + b0v;
                float y = c[mi][ni][half * 2 + 1] + b1v;
                float2 wv;
                if (chunk < 2) {
                    int jp = d >> 1;
                    float cc = g_cos[s * 32 + jp], ss = g_sin[s * 32 + jp];
                    wv.x = x * cc - y * ss;
                    wv.y = x * ss + y * cc;
                } else {
                    wv.x = x; wv.y = y;
                }
                *(float2*)&dst[(((size_t)(b * PNH + h)) * PS + s) * PHD + d] = wv;
            }
        }
    }
}

// ---------------------------------------------------------------------------
// Kernel 2: flash attention v2.
// Grid (16 q-tiles, 32 bh), 128 thr = 4 warps, warp M-tile = 32, Q in regs.
// K-tile 32. K natural [key][d] stride 68; V natural [key][d] stride 72
// (conflict-free b-frag loads); P warp-local round-trip stride 36.
// ---------------------------------------------------------------------------
__global__ __launch_bounds__(128, 2) void attention_kernel(float* __restrict__ out) {
    __shared__ uint32_t Ks[32][68];
    __shared__ uint32_t Vs[32][72];
    __shared__ uint32_t Ps[128][36];

    int t = threadIdx.x, lane = t & 31, w = t >> 5;
    int g = lane >> 2, q = lane & 3;
    int bh = blockIdx.y, q0 = blockIdx.x * 128;

    const float* Qg = g_q + (size_t)bh * PS * PHD;
    const float* Kg = g_k + (size_t)bh * PS * PHD;
    const float* Vg = g_v + (size_t)bh * PS * PHD;

    // Q fragments in registers, scale 1/8 folded in (exact pow2)
    uint32_t Qa[8][2][4];
    #pragma unroll
    for (int kf = 0; kf < 8; kf++) {
        #pragma unroll
        for (int mi = 0; mi < 2; mi++) {
            const float* base = Qg + (size_t)(q0 + 32 * w + 16 * mi + g) * 64 + kf * 8 + q;
            Qa[kf][mi][0] = f2tf(0.125f * base[0]);
            Qa[kf][mi][1] = f2tf(0.125f * base[8 * 64]);
            Qa[kf][mi][2] = f2tf(0.125f * base[4]);
            Qa[kf][mi][3] = f2tf(0.125f * base[8 * 64 + 4]);
        }
    }

    float O[2][8][4] = {};
    float mv[2][2] = {{-1e30f, -1e30f}, {-1e30f, -1e30f}};
    float lv[2][2] = {{0.0f, 0.0f}, {0.0f, 0.0f}};

    // Prefetch first K/V tile into registers
    float4 kr[4], vr[4];
    #pragma unroll
    for (int p = 0; p < 4; p++) {
        int idx = p * 128 + t, row = idx >> 4, dq = (idx & 15) * 4;
        kr[p] = *(const float4*)&Kg[(size_t)row * 64 + dq];
        vr[p] = *(const float4*)&Vg[(size_t)row * 64 + dq];
    }

    for (int kt = 0; kt < PS; kt += 32) {
        __syncthreads();   // prev iteration finished reading Ks/Vs

        // Stage current tile from registers
        #pragma unroll
        for (int p = 0; p < 4; p++) {
            int idx = p * 128 + t, row = idx >> 4, dq = (idx & 15) * 4;
            *(uint4*)&Ks[row][dq] = make_uint4(f2tf(kr[p].x), f2tf(kr[p].y), f2tf(kr[p].z), f2tf(kr[p].w));
            *(uint4*)&Vs[row][dq] = make_uint4(f2tf(vr[p].x), f2tf(vr[p].y), f2tf(vr[p].z), f2tf(vr[p].w));
        }
        __syncthreads();

        // Prefetch next tile (overlaps with all compute below)
        if (kt + 32 < PS) {
            #pragma unroll
            for (int p = 0; p < 4; p++) {
                int idx = p * 128 + t, row = idx >> 4, dq = (idx & 15) * 4;
                kr[p] = *(const float4*)&Kg[(size_t)(kt + 32 + row) * 64 + dq];
                vr[p] = *(const float4*)&Vg[(size_t)(kt + 32 + row) * 64 + dq];
            }
        }

        // S = Q K^T  (warp tile 32 x 32)
        float s[2][4][4];
        #pragma unroll
        for (int mi = 0; mi < 2; mi++)
            #pragma unroll
            for (int ni = 0; ni < 4; ni++)
                #pragma unroll
                for (int e = 0; e < 4; e++) s[mi][ni][e] = 0.0f;

        #pragma unroll
        for (int ni = 0; ni < 4; ni++) {
            #pragma unroll
            for (int kf = 0; kf < 8; kf++) {
                uint32_t b0 = Ks[ni * 8 + g][kf * 8 + q];
                uint32_t b1 = Ks[ni * 8 + g][kf * 8 + q + 4];
                mma8(s[0][ni], Qa[kf][0][0], Qa[kf][0][1], Qa[kf][0][2], Qa[kf][0][3], b0, b1);
                mma8(s[1][ni], Qa[kf][1][0], Qa[kf][1][1], Qa[kf][1][2], Qa[kf][1][3], b0, b1);
            }
        }

        // Online softmax: thread owns 4 rows (mi, h)
        #pragma unroll
        for (int mi = 0; mi < 2; mi++) {
            #pragma unroll
            for (int h = 0; h < 2; h++) {
                float ml = -1e30f;
                #pragma unroll
                for (int ni = 0; ni < 4; ni++)
                    ml = fmaxf(ml, fmaxf(s[mi][ni][2 * h], s[mi][ni][2 * h + 1]));
                ml = fmaxf(ml, __shfl_xor_sync(0xffffffffu, ml, 1));
                ml = fmaxf(ml, __shfl_xor_sync(0xffffffffu, ml, 2));

                float mnew = fmaxf(mv[mi][h], ml);
                float f = __expf(mv[mi][h] - mnew);
                mv[mi][h] = mnew;

                int row = 32 * w + 16 * mi + 8 * h + g;
                float sum = 0.0f;
                #pragma unroll
                for (int ni = 0; ni < 4; ni++) {
                    float p0 = __expf(s[mi][ni][2 * h]     - mnew);
                    float p1 = __expf(s[mi][ni][2 * h + 1] - mnew);
                    sum += p0 + p1;
                    *(uint2*)&Ps[row][ni * 8 + 2 * q] = make_uint2(f2tf(p0), f2tf(p1));
                }
                sum += __shfl_xor_sync(0xffffffffu, sum, 1);
                sum += __shfl_xor_sync(0xffffffffu, sum, 2);
                lv[mi][h] = lv[mi][h] * f + sum;

                #pragma unroll
                for (int nf = 0; nf < 8; nf++) {
                    O[mi][nf][2 * h]     *= f;
                    O[mi][nf][2 * h + 1] *= f;
                }
            }
        }
        __syncwarp();

        // O += P V
        #pragma unroll
        for (int kf = 0; kf < 4; kf++) {
            uint32_t a[2][4];
            #pragma unroll
            for (int mi = 0; mi < 2; mi++) {
                int r = 32 * w + 16 * mi + g;
                a[mi][0] = Ps[r][kf * 8 + q];
                a[mi][1] = Ps[r + 8][kf * 8 + q];
                a[mi][2] = Ps[r][kf * 8 + q + 4];
                a[mi][3] = Ps[r + 8][kf * 8 + q + 4];
            }
            #pragma unroll
            for (int nf = 0; nf < 8; nf++) {
                uint32_t b0 = Vs[kf * 8 + q][nf * 8 + g];
                uint32_t b1 = Vs[kf * 8 + q + 4][nf * 8 + g];
                mma8(O[0][nf], a[0][0], a[0][1], a[0][2], a[0][3], b0, b1);
                mma8(O[1][nf], a[1][0], a[1][1], a[1][2], a[1][3], b0, b1);
            }
        }
    }

    // Epilogue
    int b = bh >> 4, hh = bh & 15;
    #pragma unroll
    for (int mi = 0; mi < 2; mi++) {
        #pragma unroll
        for (int h = 0; h < 2; h++) {
            float inv = 1.0f / lv[mi][h];
            int srow = q0 + 32 * w + 16 * mi + 8 * h + g;
            #pragma unroll
            for (int nf = 0; nf < 8; nf++) {
                float2 wv = make_float2(O[mi][nf][2 * h] * inv, O[mi][nf][2 * h + 1] * inv);
                *(float2*)&out[((size_t)(b * PS + srow)) * PE + hh * 64 + nf * 8 + 2 * q] = wv;
            }
        }
    }
}

// ---------------------------------------------------------------------------
extern "C" void kernel_launch(void* const* d_in, const int* in_sizes, int n_in,
                              void* d_out, int out_size) {
    const float* hs   = (const float*)d_in[0];
    const float* w    = (const float*)d_in[1];
    const float* bias = (const float*)d_in[2];
    float* out = (float*)d_out;

    rope_table_kernel<<<256, 256>>>();
    qkv_gemm_kernel<<<dim3(24, 32), 256>>>(hs, w, bias);
    attention_kernel<<<dim3(16, 32), 128>>>(out);
}